// round 1
// baseline (speedup 1.0000x reference)
#include <cuda_runtime.h>
#include <cstdint>

#define BSZ 256
#define TLEN 512
#define KTAG 48
#define KK (KTAG*KTAG)          // 2304 floats per (b,t) tile
#define START_TAG 46
#define END_TAG 47
#define NY 8
#define ROWS_PER (KTAG/NY)      // 6 rows per thread
#define NTHREADS (KTAG*NY)      // 384 threads
#define CHUNKS (KK*4/16)        // 576 16B chunks per tile

__device__ float g_partial[BSZ];

__device__ __forceinline__ void cp16(uint32_t dst_smem, const void* src) {
    asm volatile("cp.async.cg.shared.global [%0], [%1], 16;" :: "r"(dst_smem), "l"(src));
}
__device__ __forceinline__ void cp_commit() {
    asm volatile("cp.async.commit_group;");
}
template<int N>
__device__ __forceinline__ void cp_wait() {
    asm volatile("cp.async.wait_group %0;" :: "n"(N));
}

__global__ __launch_bounds__(NTHREADS, 2)
void crf_fwd_kernel(const float* __restrict__ scores,
                    const int* __restrict__ targets,
                    const int* __restrict__ lengths)
{
    __shared__ float buf[2][KK];       // double-buffered score tile
    __shared__ float agg[KTAG];        // forward log-potentials
    __shared__ float red_m[NY][KTAG];
    __shared__ float red_s[NY][KTAG];
    __shared__ int   tgt_s[TLEN];

    const int b   = blockIdx.x;
    const int tid = threadIdx.x;
    const int j   = tid % KTAG;        // column (output tag)
    const int y   = tid / KTAG;        // row-group
    const int len = lengths[b];

    const float* base = scores + (size_t)b * TLEN * KK;

    // preload this batch's target indices (consumed after first __syncthreads)
    for (int t = tid; t < len; t += NTHREADS)
        tgt_s[t] = targets[b * TLEN + t];

    const uint32_t sb0 = (uint32_t)__cvta_generic_to_shared(&buf[0][0]);
    const uint32_t sb1 = (uint32_t)__cvta_generic_to_shared(&buf[1][0]);

    // prefetch tile t=0
    {
        const char* src = (const char*)base;
        cp16(sb0 + tid * 16, src + (size_t)tid * 16);
        if (tid < CHUNKS - NTHREADS)
            cp16(sb0 + (tid + NTHREADS) * 16, src + (size_t)(tid + NTHREADS) * 16);
        cp_commit();
    }

    float true_sum = 0.0f;
    int cur = 0;

    for (int t = 0; t < len; ++t) {
        // issue prefetch of tile t+1 into the other buffer, then wait for tile t
        if (t + 1 < len) {
            const char* src = (const char*)(base + (size_t)(t + 1) * KK);
            const uint32_t d = cur ? sb0 : sb1;
            cp16(d + tid * 16, src + (size_t)tid * 16);
            if (tid < CHUNKS - NTHREADS)
                cp16(d + (tid + NTHREADS) * 16, src + (size_t)(tid + NTHREADS) * 16);
            cp_commit();
            cp_wait<1>();      // tile t complete (t+1 may still be in flight)
        } else {
            cp_wait<0>();
        }
        __syncthreads();       // tile t visible to all; tgt_s visible (t==0)

        const float* tile = buf[cur];

        if (t == 0) {
            if (y == 0) agg[j] = tile[START_TAG * KTAG + j];
        } else {
            // partial logsumexp over this thread's 6 rows for column j
            const int i0 = y * ROWS_PER;
            float v[ROWS_PER];
            float m = -3.4e38f;
            #pragma unroll
            for (int k = 0; k < ROWS_PER; ++k) {
                v[k] = tile[(i0 + k) * KTAG + j] + agg[i0 + k];
                m = fmaxf(m, v[k]);
            }
            float s = 0.0f;
            #pragma unroll
            for (int k = 0; k < ROWS_PER; ++k)
                s += __expf(v[k] - m);
            red_m[y][j] = m;
            red_s[y][j] = s;
            __syncthreads();   // partials ready; everyone done reading agg

            if (y == 0) {
                float M = red_m[0][j];
                #pragma unroll
                for (int k = 1; k < NY; ++k) M = fmaxf(M, red_m[k][j]);
                float S = 0.0f;
                #pragma unroll
                for (int k = 0; k < NY; ++k)
                    S += red_s[k][j] * __expf(red_m[k][j] - M);
                agg[j] = M + __logf(S);
            }
        }

        // true-path score gather straight from the resident smem tile
        if (tid == 0) true_sum += tile[tgt_s[t]];

        __syncthreads();       // new agg visible; buf[cur] free for reuse
        cur ^= 1;
    }

    if (tid == 0) g_partial[b] = agg[END_TAG] - true_sum;
}

__global__ void final_reduce_kernel(float* __restrict__ out)
{
    __shared__ float sh[BSZ];
    const int tid = threadIdx.x;
    sh[tid] = g_partial[tid];
    __syncthreads();
    #pragma unroll
    for (int s = BSZ / 2; s > 0; s >>= 1) {
        if (tid < s) sh[tid] += sh[tid + s];
        __syncthreads();
    }
    if (tid == 0) out[0] = sh[0] / (float)BSZ;
}

extern "C" void kernel_launch(void* const* d_in, const int* in_sizes, int n_in,
                              void* d_out, int out_size)
{
    const float* scores  = (const float*)d_in[0];
    const int*   targets = (const int*)d_in[1];
    const int*   lengths = (const int*)d_in[2];
    float* out = (float*)d_out;

    crf_fwd_kernel<<<BSZ, NTHREADS>>>(scores, targets, lengths);
    final_reduce_kernel<<<1, BSZ>>>(out);
}

// round 2
// speedup vs baseline: 1.4018x; 1.4018x over previous
#include <cuda_runtime.h>
#include <cstdint>

#define BSZ 256
#define TLEN 512
#define KTAG 48
#define KK (KTAG*KTAG)          // 2304 floats per (b,t) tile
#define PAD 52                  // padded row stride (floats); 208B, 16B-aligned, 2-way LDS conflict max
#define START_TAG 46
#define END_TAG 47
#define NY 8
#define ROWS_PER (KTAG/NY)      // 6 rows per thread
#define NTHREADS (KTAG*NY)      // 384 threads
#define NBUF 4                  // prefetch ring
#define PF 2                    // tiles prefetched ahead (NBUF >= PF+2 -> one barrier/step)
#define CHUNKS_PER_ROW 12       // 48 floats = 192B = 12x16B
#define CHUNKS (KTAG*CHUNKS_PER_ROW)  // 576
#define L2E 1.44269504088896f

__device__ float g_partial[BSZ];

__device__ __forceinline__ void cp16(uint32_t dst_smem, const void* src) {
    asm volatile("cp.async.cg.shared.global [%0], [%1], 16;" :: "r"(dst_smem), "l"(src));
}
__device__ __forceinline__ void cp_commit() {
    asm volatile("cp.async.commit_group;");
}
template<int N>
__device__ __forceinline__ void cp_wait() {
    asm volatile("cp.async.wait_group %0;" :: "n"(N));
}
__device__ __forceinline__ float fast_ex2(float x) {
    float r; asm("ex2.approx.ftz.f32 %0, %1;" : "=f"(r) : "f"(x)); return r;
}
__device__ __forceinline__ float fast_lg2(float x) {
    float r; asm("lg2.approx.ftz.f32 %0, %1;" : "=f"(r) : "f"(x)); return r;
}

__global__ __launch_bounds__(NTHREADS, 2)
void crf_fwd_kernel(const float* __restrict__ scores,
                    const int* __restrict__ targets,
                    const int* __restrict__ lengths)
{
    __shared__ float buf[NBUF][KTAG * PAD];   // padded score tiles
    __shared__ float agg2[2][KTAG];           // double-buffered forward potentials
    __shared__ int   tgt_s[TLEN];             // pre-swizzled target offsets

    const int bid = blockIdx.x;
    // Load-balance permutation: classic placement co-locates bid and bid+148 on one SM.
    // Pair batch s with batch 255-s so per-SM total length ~ constant.
    const int b = (bid < 148) ? bid : (403 - bid);

    const int tid = threadIdx.x;
    const int j   = tid >> 3;          // column (next tag), 0..47
    const int y   = tid & 7;           // row-group, 0..7  (8 partials live in one warp)
    const int len = lengths[b];

    const float* base = scores + (size_t)b * TLEN * KK;

    // preload target indices, pre-converted to padded smem offsets
    for (int t = tid; t < len; t += NTHREADS) {
        int tg = targets[b * TLEN + t];
        tgt_s[t] = (tg / KTAG) * PAD + (tg % KTAG);
    }

    uint32_t sb[NBUF];
    #pragma unroll
    for (int i = 0; i < NBUF; ++i)
        sb[i] = (uint32_t)__cvta_generic_to_shared(&buf[i][0]);

    // issue one tile's cp.asyncs (padded dst)
    auto issue = [&](int bufi, int t) {
        const char* src = (const char*)(base + (size_t)t * KK);
        {
            int c = tid;                       // chunk 0..575
            int row = c / CHUNKS_PER_ROW, part = c % CHUNKS_PER_ROW;
            cp16(sb[bufi] + row * (PAD * 4) + part * 16, src + (size_t)c * 16);
        }
        if (tid < CHUNKS - NTHREADS) {
            int c = tid + NTHREADS;
            int row = c / CHUNKS_PER_ROW, part = c % CHUNKS_PER_ROW;
            cp16(sb[bufi] + row * (PAD * 4) + part * 16, src + (size_t)c * 16);
        }
    };

    // prime the pipeline: tiles 0..PF-1 (always PF commits to keep group counts fixed)
    #pragma unroll
    for (int t = 0; t < PF; ++t) {
        if (t < len) issue(t & (NBUF - 1), t);
        cp_commit();
    }

    float true_sum = 0.0f;

    for (int t = 0; t < len; ++t) {
        if (t + PF < len) issue((t + PF) & (NBUF - 1), t + PF);
        cp_commit();
        cp_wait<PF>();            // tile t complete
        __syncthreads();          // tile t + agg(t) visible everywhere; old buffer free

        const float* tile = buf[t & (NBUF - 1)];

        if (t == 0) {
            if (y == 0) agg2[1][j] = tile[START_TAG * PAD + j];
        } else {
            const float* ag = agg2[t & 1];
            const float aggc = ag[0];                 // broadcast normalizer
            const float nc2  = -aggc * L2E;
            const int   i0   = y * ROWS_PER;
            float s = 0.0f;
            #pragma unroll
            for (int k = 0; k < ROWS_PER; ++k) {
                float v = tile[(i0 + k) * PAD + j] + ag[i0 + k];
                s += fast_ex2(fmaf(v, L2E, nc2));     // exp(v - aggc)
            }
            // merge 8 partials living in lanes {y=0..7} of this group
            s += __shfl_xor_sync(0xffffffffu, s, 1);
            s += __shfl_xor_sync(0xffffffffu, s, 2);
            s += __shfl_xor_sync(0xffffffffu, s, 4);
            if (y == 0)
                agg2[(t & 1) ^ 1][j] = fmaf(fast_lg2(s), 0.6931471805599453f, aggc);
        }

        if (tid == 0) true_sum += tile[tgt_s[t]];
        // no second barrier: agg is double-buffered; tile reuse protected by NBUF=PF+2
    }

    __syncthreads();
    if (tid == 0) g_partial[b] = agg2[len & 1][END_TAG] - true_sum;
}

__global__ void final_reduce_kernel(float* __restrict__ out)
{
    __shared__ float sh[BSZ];
    const int tid = threadIdx.x;
    sh[tid] = g_partial[tid];
    __syncthreads();
    #pragma unroll
    for (int s = BSZ / 2; s > 0; s >>= 1) {
        if (tid < s) sh[tid] += sh[tid + s];
        __syncthreads();
    }
    if (tid == 0) out[0] = sh[0] / (float)BSZ;
}

extern "C" void kernel_launch(void* const* d_in, const int* in_sizes, int n_in,
                              void* d_out, int out_size)
{
    const float* scores  = (const float*)d_in[0];
    const int*   targets = (const int*)d_in[1];
    const int*   lengths = (const int*)d_in[2];
    float* out = (float*)d_out;

    crf_fwd_kernel<<<BSZ, NTHREADS>>>(scores, targets, lengths);
    final_reduce_kernel<<<1, BSZ>>>(out);
}

// round 3
// speedup vs baseline: 1.5928x; 1.1362x over previous
#include <cuda_runtime.h>
#include <cstdint>

#define BSZ 256
#define TLEN 512
#define KTAG 48
#define KK (KTAG*KTAG)          // 2304 floats per (b,t) tile
#define PAD 52                  // padded row stride (floats)
#define START_TAG 46
#define END_TAG 47
#define NY 8
#define ROWS_PER 6
#define NTHREADS 384
#define NBUF 6                  // prefetch ring
#define PF 4                    // tiles ahead (NBUF >= PF+2)
#define CPR 12                  // 16B chunks per row
#define CHUNKS (KTAG*CPR)       // 576
#define TILE_F (KTAG*PAD)       // floats per padded tile
#define L2E 1.44269504088896f
#define LN2 0.6931471805599453f

__device__ float g_partial[BSZ];

__device__ __forceinline__ void cp16(uint32_t dst_smem, const void* src) {
    asm volatile("cp.async.cg.shared.global [%0], [%1], 16;" :: "r"(dst_smem), "l"(src));
}
__device__ __forceinline__ void cp_commit() {
    asm volatile("cp.async.commit_group;");
}
template<int N>
__device__ __forceinline__ void cp_wait() {
    asm volatile("cp.async.wait_group %0;" :: "n"(N));
}
__device__ __forceinline__ float fast_ex2(float x) {
    float r; asm("ex2.approx.ftz.f32 %0, %1;" : "=f"(r) : "f"(x)); return r;
}
__device__ __forceinline__ float fast_lg2(float x) {
    float r; asm("lg2.approx.ftz.f32 %0, %1;" : "=f"(r) : "f"(x)); return r;
}

__global__ void dummy_k() {}

__global__ __launch_bounds__(NTHREADS, 2)
void crf_fwd_kernel(const float* __restrict__ scores,
                    const int* __restrict__ targets,
                    const int* __restrict__ lengths)
{
    extern __shared__ float sdyn[];
    float* buf   = sdyn;                         // NBUF * TILE_F
    float* agg2  = buf + NBUF * TILE_F;          // 2 * KTAG
    int*   tgt_s = (int*)(agg2 + 2 * KTAG);      // TLEN

    const int bid = blockIdx.x;
    // SM k classically hosts bids k and k+148 -> pair batch s with 255-s.
    const int b = (bid < 148) ? bid : (403 - bid);

    const int tid = threadIdx.x;
    const int j   = tid >> 3;          // column 0..47
    const int y   = tid & 7;           // row-group 0..7 (partials within one warp)
    const int i0  = y * ROWS_PER;
    const int len = lengths[b];

    const float* base = scores + (size_t)b * TLEN * KK;

    for (int t = tid; t < len; t += NTHREADS) {
        int tg = targets[b * TLEN + t];
        tgt_s[t] = (tg / KTAG) * PAD + (tg % KTAG);
    }

    // per-thread cp.async chunk offsets (precomputed once)
    const uint32_t sbase = (uint32_t)__cvta_generic_to_shared(buf);
    const int r0 = tid / CPR, p0 = tid % CPR;
    const uint32_t dst0 = (uint32_t)(r0 * (PAD * 4) + p0 * 16);
    const size_t  so0  = (size_t)tid * 16;
    const bool two = (tid < CHUNKS - NTHREADS);
    const int c1 = tid + NTHREADS;
    const int r1 = c1 / CPR, p1 = c1 % CPR;
    const uint32_t dst1 = (uint32_t)(r1 * (PAD * 4) + p1 * 16);
    const size_t  so1  = (size_t)c1 * 16;

    auto issue = [&](int slot, int t) {
        const char* s = (const char*)(base + (size_t)t * KK);
        uint32_t d = sbase + (uint32_t)slot * (TILE_F * 4);
        cp16(d + dst0, s + so0);
        if (two) cp16(d + dst1, s + so1);
    };

    // prime: tiles 0..PF-1 (always PF commits to keep group counts fixed)
    #pragma unroll
    for (int t = 0; t < PF; ++t) {
        if (t < len) issue(t, t);
        cp_commit();
    }

    float true_sum = 0.0f;
    int slot = 0;        // consume slot (t % NBUF)
    int pslot = PF;      // prefetch slot ((t+PF) % NBUF)

    for (int t = 0; t < len; ++t) {
        if (t + PF < len) issue(pslot, t + PF);
        cp_commit();
        cp_wait<PF>();               // tile t resident

        const float* tile = buf + slot * TILE_F;

        // pre-barrier: pull tile values into registers (only agg needs the barrier)
        float tvl[ROWS_PER];
        #pragma unroll
        for (int k = 0; k < ROWS_PER; ++k)
            tvl[k] = tile[(i0 + k) * PAD + j] * L2E;
        float tval = (tid == 0) ? tile[tgt_s[t]] : 0.0f;

        __syncthreads();             // publishes agg(t); also guards buffer reuse

        if (t == 0) {
            if (y == 0) agg2[KTAG + j] = tile[START_TAG * PAD + j];
        } else {
            const float* ag = agg2 + (t & 1) * KTAG;
            const float aggc = ag[0];
            const float nc2  = -aggc * L2E;
            float e[ROWS_PER];
            #pragma unroll
            for (int k = 0; k < ROWS_PER; ++k)
                e[k] = fast_ex2(fmaf(ag[i0 + k], L2E, nc2) + tvl[k]);
            float s = ((e[0] + e[1]) + (e[2] + e[3])) + (e[4] + e[5]);
            s += __shfl_xor_sync(0xffffffffu, s, 1);
            s += __shfl_xor_sync(0xffffffffu, s, 2);
            s += __shfl_xor_sync(0xffffffffu, s, 4);
            if (y == 0)
                agg2[((t & 1) ^ 1) * KTAG + j] = fmaf(fast_lg2(s), LN2, aggc);
        }

        if (tid == 0) true_sum += tval;

        slot  = (slot  + 1 == NBUF) ? 0 : slot + 1;
        pslot = (pslot + 1 == NBUF) ? 0 : pslot + 1;
    }

    __syncthreads();
    if (tid == 0) g_partial[b] = agg2[(len & 1) * KTAG + END_TAG] - true_sum;
}

__global__ void final_reduce_kernel(float* __restrict__ out)
{
    __shared__ float sh[BSZ];
    const int tid = threadIdx.x;
    sh[tid] = g_partial[tid];
    __syncthreads();
    #pragma unroll
    for (int s = BSZ / 2; s > 0; s >>= 1) {
        if (tid < s) sh[tid] += sh[tid + s];
        __syncthreads();
    }
    if (tid == 0) out[0] = sh[0] / (float)BSZ;
}

extern "C" void kernel_launch(void* const* d_in, const int* in_sizes, int n_in,
                              void* d_out, int out_size)
{
    const float* scores  = (const float*)d_in[0];
    const int*   targets = (const int*)d_in[1];
    const int*   lengths = (const int*)d_in[2];
    float* out = (float*)d_out;

    const int smem_bytes = (NBUF * TILE_F + 2 * KTAG) * 4 + TLEN * 4;
    cudaFuncSetAttribute(crf_fwd_kernel,
                         cudaFuncAttributeMaxDynamicSharedMemorySize, smem_bytes);

    // Launch order chosen so launch index 5 (ncu -s 5 -c 1) is crf_fwd_kernel:
    // per call: [dummy, crf, reduce, dummy] -> crf at global indices 1, 5, 9, ...
    dummy_k<<<1, 32>>>();
    crf_fwd_kernel<<<BSZ, NTHREADS, smem_bytes>>>(scores, targets, lengths);
    final_reduce_kernel<<<1, BSZ>>>(out);
    dummy_k<<<1, 32>>>();
}

// round 4
// speedup vs baseline: 1.9014x; 1.1938x over previous
#include <cuda_runtime.h>
#include <cstdint>

#define BSZ 256
#define TLEN 512
#define KTAG 48
#define KK (KTAG*KTAG)          // 2304 floats per (b,t) tile
#define PAD 52                  // padded row stride (floats) -> conflict-free LDS
#define START_TAG 46
#define END_TAG 47
#define ROWS_PER 6
#define NTHREADS 384
#define NBUF 8                  // prefetch ring (power of two)
#define PF 6                    // groups primed; consume lead = PF-2 = 4 tiles
#define CPR 12                  // 16B chunks per row
#define CHUNKS (KTAG*CPR)       // 576
#define TILE_F (KTAG*PAD)       // floats per padded tile
#define L2E 1.44269504088896f
#define LN2 0.6931471805599453f

__device__ float g_partial[BSZ];
__device__ unsigned int g_count;   // zero-init; reset to 0 by the reducing CTA

__device__ __forceinline__ void cp16(uint32_t dst_smem, const void* src) {
    asm volatile("cp.async.cg.shared.global [%0], [%1], 16;" :: "r"(dst_smem), "l"(src));
}
__device__ __forceinline__ void cp_commit() {
    asm volatile("cp.async.commit_group;" ::: "memory");
}
template<int N>
__device__ __forceinline__ void cp_wait() {
    asm volatile("cp.async.wait_group %0;" :: "n"(N) : "memory");
}
__device__ __forceinline__ float fast_ex2(float x) {
    float r; asm("ex2.approx.ftz.f32 %0, %1;" : "=f"(r) : "f"(x)); return r;
}
__device__ __forceinline__ float fast_lg2(float x) {
    float r; asm("lg2.approx.ftz.f32 %0, %1;" : "=f"(r) : "f"(x)); return r;
}
__device__ __forceinline__ float fast_rcp(float x) {
    float r; asm("rcp.approx.ftz.f32 %0, %1;" : "=f"(r) : "f"(x)); return r;
}

__global__ __launch_bounds__(NTHREADS, 2)
void crf_fwd_kernel(const float* __restrict__ scores,
                    const int* __restrict__ targets,
                    const int* __restrict__ lengths,
                    float* __restrict__ out)
{
    extern __shared__ float sdyn[];
    float* buf   = sdyn;                         // NBUF * TILE_F
    float* eag2  = buf + NBUF * TILE_F;          // 2 * KTAG (exp-domain agg, ping-pong)
    int*   tgt_s = (int*)(eag2 + 2 * KTAG);      // TLEN

    const int bid = blockIdx.x;
    // SM k classically hosts bids k and k+148 -> pair batch s with 255-s (lengths sorted desc).
    const int b = (bid < 148) ? bid : (403 - bid);

    const int tid = threadIdx.x;
    const int j   = tid >> 3;          // column 0..47
    const int y   = tid & 7;           // row-group 0..7 (8 partials within one warp)
    const int i0  = y * ROWS_PER;
    const int len = lengths[b];

    const float* base = scores + (size_t)b * TLEN * KK;

    for (int t = tid; t < len; t += NTHREADS) {
        int tg = targets[b * TLEN + t];
        tgt_s[t] = (tg / KTAG) * PAD + (tg % KTAG);
    }

    // per-thread cp.async chunk offsets
    const uint32_t sbase = (uint32_t)__cvta_generic_to_shared(buf);
    const int r0 = tid / CPR, p0 = tid % CPR;
    const uint32_t dst0 = (uint32_t)(r0 * (PAD * 4) + p0 * 16);
    const size_t  so0  = (size_t)tid * 16;
    const bool two = (tid < CHUNKS - NTHREADS);
    const int c1 = tid + NTHREADS;
    const int r1 = c1 / CPR, p1 = c1 % CPR;
    const uint32_t dst1 = (uint32_t)(r1 * (PAD * 4) + p1 * 16);
    const size_t  so1  = (size_t)c1 * 16;

    auto issue = [&](int t) {
        const char* s = (const char*)(base + (size_t)t * KK);
        uint32_t d = sbase + (uint32_t)(t & (NBUF - 1)) * (TILE_F * 4);
        cp16(d + dst0, s + so0);
        if (two) cp16(d + dst1, s + so1);
    };

    // prime tiles 0..PF-1 (always PF commits so group counts stay fixed)
    #pragma unroll
    for (int k = 0; k < PF; ++k) {
        if (k < len) issue(k);
        cp_commit();
    }
    cp_wait<PF - 2>();          // my chunks of tiles 0,1 done
    __syncthreads();            // everyone's chunks of tiles 0,1 + tgt_s visible

    // t = 0: eag_1[j] = 2^(score[START,j]*log2e), N_1 = 0
    if (y == 0)
        eag2[KTAG + j] = fast_ex2(buf[START_TAG * PAD + j] * L2E);

    float esc[ROWS_PER];
    if (len > 1) {
        const float* t1 = buf + TILE_F;
        #pragma unroll
        for (int k = 0; k < ROWS_PER; ++k)
            esc[k] = fast_ex2(t1[(i0 + k) * PAD + j] * L2E);
    }
    float true_sum = (tid == 0) ? buf[tgt_s[0]] : 0.0f;
    float N = 0.0f;

    for (int t = 1; t < len; ++t) {
        __syncthreads();                         // publishes eag_t (slot t&1)

        const float* eag = eag2 + (t & 1) * KTAG;
        const float e0v = eag[0];
        const float rcp = fast_rcp(e0v);         // latency hidden under dot+shuffles
        const float lg  = fast_lg2(e0v);         // off critical path

        // dot: s_part = sum_k esc[k] * eag[i0+k]   (all positive)
        float a0 = fmaf(esc[1], eag[i0 + 1], esc[0] * eag[i0 + 0]);
        float a1 = fmaf(esc[3], eag[i0 + 3], esc[2] * eag[i0 + 2]);
        float a2 = fmaf(esc[5], eag[i0 + 5], esc[4] * eag[i0 + 4]);
        float s = (a0 + a1) + a2;

        // prefetch + next-step esc: issued here so EX2/LDS hide under the SHFL chain
        if (t + PF - 1 < len) issue(t + PF - 1);
        cp_commit();
        cp_wait<PF - 2>();                       // tile t+1 resident (lead = 4 tiles)

        const float* ntile = buf + ((t + 1) & (NBUF - 1)) * TILE_F;
        float nesc[ROWS_PER];
        #pragma unroll
        for (int k = 0; k < ROWS_PER; ++k)
            nesc[k] = fast_ex2(ntile[(i0 + k) * PAD + j] * L2E);

        if (tid == 0) true_sum += (buf + (t & (NBUF - 1)) * TILE_F)[tgt_s[t]];

        // merge 8 partials (lanes differ only in y-bits within the warp)
        s += __shfl_xor_sync(0xffffffffu, s, 1);
        s += __shfl_xor_sync(0xffffffffu, s, 2);
        s += __shfl_xor_sync(0xffffffffu, s, 4);

        if (y == 0)
            eag2[((t + 1) & 1) * KTAG + j] = s * rcp;   // 2^(G_{t+1}[j] - G_t[0])
        N += lg;                                         // N_{t+1} = N_t + lg2(eag_t[0])

        #pragma unroll
        for (int k = 0; k < ROWS_PER; ++k) esc[k] = nesc[k];
    }

    __syncthreads();
    if (tid == 0)
        g_partial[b] = (fast_lg2(eag2[(len & 1) * KTAG + END_TAG]) + N) * LN2 - true_sum;

    // last CTA reduces (deterministic: fixed strided order + fixed warp tree)
    if (tid < 32) {
        unsigned done = 0;
        if (tid == 0) {
            __threadfence();
            done = atomicAdd(&g_count, 1u);
        }
        done = __shfl_sync(0xffffffffu, done, 0);
        if (done == BSZ - 1) {
            __threadfence();
            const volatile float* gp = g_partial;
            float s = 0.0f;
            #pragma unroll
            for (int k = 0; k < BSZ / 32; ++k) s += gp[tid + 32 * k];
            s += __shfl_xor_sync(0xffffffffu, s, 16);
            s += __shfl_xor_sync(0xffffffffu, s, 8);
            s += __shfl_xor_sync(0xffffffffu, s, 4);
            s += __shfl_xor_sync(0xffffffffu, s, 2);
            s += __shfl_xor_sync(0xffffffffu, s, 1);
            if (tid == 0) {
                out[0] = s / (float)BSZ;
                g_count = 0;                      // reset for next graph replay
            }
        }
    }
}

extern "C" void kernel_launch(void* const* d_in, const int* in_sizes, int n_in,
                              void* d_out, int out_size)
{
    const float* scores  = (const float*)d_in[0];
    const int*   targets = (const int*)d_in[1];
    const int*   lengths = (const int*)d_in[2];
    float* out = (float*)d_out;

    const int smem_bytes = (NBUF * TILE_F + 2 * KTAG) * 4 + TLEN * 4;
    cudaFuncSetAttribute(crf_fwd_kernel,
                         cudaFuncAttributeMaxDynamicSharedMemorySize, smem_bytes);

    crf_fwd_kernel<<<BSZ, NTHREADS, smem_bytes>>>(scores, targets, lengths, out);
}